// round 8
// baseline (speedup 1.0000x reference)
#include <cuda_runtime.h>
#include <cuda_bf16.h>

#define BATCH 32
#define NAG   6
#define KS    256
#define QS    256
#define CHW   (512*32*32)       /* 524288 floats per (b,n) slab */
#define V4PB  (CHW/4)           /* 131072 float4 per (b,n) slab */
#define CHUNKS 8                /* attn kk-chunks per batch (32 rows each) */
#define TILES 4096              /* wsum tiles: 1024 float4 each */
#define GRID  740               /* 148 SMs x 5 blocks: one wave at ~48 regs */

// Scratch (allocation-free rule: __device__ globals). All counters are reset
// inside the kernel so every graph replay starts from identical state.
__device__ float        g_attn[BATCH * NAG];
__device__ float        g_score[BATCH * NAG];
__device__ unsigned int g_cnt[BATCH];
__device__ unsigned int g_ready;     // # batches finalized (0..32)
__device__ unsigned int g_fin;       // # blocks finished (0..GRID)

// ---------------------------------------------------------------------------
// Persistent fused kernel, grid = 740 x 256 (single wave).
//  * blocks 0..255 first run one attn chunk (batch bid>>3, rows (bid&7)*32..):
//      query rows via warp dots -> partial agent scores -> atomicAdd;
//      ticketed finalizer per batch: sparsemax -> g_attn -> g_ready++.
//  * all blocks: spin until g_ready==32, stage all 192 weights in smem,
//      then grid-stride over 4096 tiles: out[b,:] = sum_n w[b,n]*v[b,n,:]
//      (zero-weight agents skipped; branch is block-uniform per tile).
//  * last finishing block resets g_ready/g_fin for the next graph replay.
// ---------------------------------------------------------------------------
__global__ void __launch_bounds__(256)
fused_kernel(const float* __restrict__ q,
             const float* __restrict__ k,
             const float* __restrict__ v,
             const float* __restrict__ W,
             const float* __restrict__ bias,
             float* __restrict__ out,
             float* __restrict__ out_attn,
             int write_attn) {
    const int bid  = blockIdx.x;
    const int t    = threadIdx.x;
    const int wid  = t >> 5, lane = t & 31;

    __shared__ float4 sq4[QS / 4];
    __shared__ float  squery[32];
    __shared__ float  sw[BATCH * NAG];     // all weights, staged once

    // ================= attn phase (blocks 0..255 only) ====================
    if (bid < BATCH * CHUNKS) {
        const int ab     = bid >> 3;
        const int kkbase = (bid & 7) << 5;

        if (t < QS / 4) sq4[t] = ((const float4*)(q + ab * QS))[t];
        __syncthreads();

        // warp `wid` computes 4 query rows, 2 at a time
        {
            const int r0 = kkbase + (wid << 2);
            const float4 q0 = sq4[lane], q1 = sq4[lane + 32];
            #pragma unroll
            for (int h = 0; h < 2; h++) {
                const int ra = r0 + 2 * h;
                const float4* wa = (const float4*)(W + ra * QS);
                const float4* wb = (const float4*)(W + (ra + 1) * QS);
                float4 a0 = wa[lane], a1 = wa[lane + 32];
                float4 b0 = wb[lane], b1 = wb[lane + 32];
                float sa = a0.x * q0.x + a0.y * q0.y + a0.z * q0.z + a0.w * q0.w
                         + a1.x * q1.x + a1.y * q1.y + a1.z * q1.z + a1.w * q1.w;
                float sb = b0.x * q0.x + b0.y * q0.y + b0.z * q0.z + b0.w * q0.w
                         + b1.x * q1.x + b1.y * q1.y + b1.z * q1.z + b1.w * q1.w;
                #pragma unroll
                for (int o = 16; o; o >>= 1) {
                    sa += __shfl_xor_sync(0xffffffffu, sa, o);
                    sb += __shfl_xor_sync(0xffffffffu, sb, o);
                }
                if (lane == 0) {
                    squery[(wid << 2) + 2 * h]     = sa + bias[ra];
                    squery[(wid << 2) + 2 * h + 1] = sb + bias[ra + 1];
                }
            }
        }
        __syncthreads();

        // 6 warps -> partial agent scores
        if (wid < NAG) {
            float p = k[(ab * NAG + wid) * KS + kkbase + lane] * squery[lane];
            #pragma unroll
            for (int o = 16; o; o >>= 1) p += __shfl_xor_sync(0xffffffffu, p, o);
            if (lane == 0) atomicAdd(&g_score[ab * NAG + wid], p);
        }

        __threadfence();
        if (t == 0 && atomicAdd(&g_cnt[ab], 1u) == CHUNKS - 1) {
            __threadfence();                      // acquire all partials
            float z[NAG], zs[NAG];
            #pragma unroll
            for (int n = 0; n < NAG; n++) {
                z[n] = g_score[ab * NAG + n];
                zs[n] = z[n];
                g_score[ab * NAG + n] = 0.0f;     // reset for next replay
            }
            g_cnt[ab] = 0u;
            #pragma unroll
            for (int i = 1; i < NAG; i++) {       // insertion sort, descending
                float key = zs[i]; int j = i - 1;
                while (j >= 0 && zs[j] < key) { zs[j + 1] = zs[j]; j--; }
                zs[j + 1] = key;
            }
            float cs[NAG], run = 0.f;
            #pragma unroll
            for (int r = 0; r < NAG; r++) { run += zs[r]; cs[r] = run; }
            int kk = 0;
            #pragma unroll
            for (int r = 1; r <= NAG; r++)
                if (1.0f + (float)r * zs[r - 1] > cs[r - 1]) kk++;
            const float tau = (cs[kk - 1] - 1.0f) / (float)kk;
            #pragma unroll
            for (int n = 0; n < NAG; n++) {
                float p = fmaxf(z[n] - tau, 0.0f);
                g_attn[ab * NAG + n] = p;
                if (write_attn) out_attn[ab * NAG + n] = p;
            }
            __threadfence();                      // publish before counting
            atomicAdd(&g_ready, 1u);
        }
        __syncthreads();
    }

    // ================= wait once, stage all weights =======================
    if (t == 0) {
        while (*((volatile unsigned int*)&g_ready) != BATCH) __nanosleep(64);
    }
    __syncthreads();
    if (t < BATCH * NAG) sw[t] = __ldcg(&g_attn[t]);
    __syncthreads();

    // ================= persistent wsum loop ===============================
    for (int tau = bid; tau < TILES; tau += GRID) {
        const int b    = tau >> 7;                       // 128 tiles/batch
        const int base = ((tau & 127) << 10) + t;        // float4 idx in slab

        const float4* vb = (const float4*)v + (b * (NAG * V4PB) + base);

        float4 acc0 = make_float4(0.f, 0.f, 0.f, 0.f);
        float4 acc1 = acc0, acc2 = acc0, acc3 = acc0;

        #pragma unroll
        for (int n = 0; n < NAG; n++) {
            const float w = sw[b * NAG + n];
            if (w != 0.0f) {                  // block-uniform branch
                const float4* p = vb + n * V4PB;
                float4 x0 = __ldcs(p);
                float4 x1 = __ldcs(p + 256);
                float4 x2 = __ldcs(p + 512);
                float4 x3 = __ldcs(p + 768);
                acc0.x = fmaf(w, x0.x, acc0.x); acc0.y = fmaf(w, x0.y, acc0.y);
                acc0.z = fmaf(w, x0.z, acc0.z); acc0.w = fmaf(w, x0.w, acc0.w);
                acc1.x = fmaf(w, x1.x, acc1.x); acc1.y = fmaf(w, x1.y, acc1.y);
                acc1.z = fmaf(w, x1.z, acc1.z); acc1.w = fmaf(w, x1.w, acc1.w);
                acc2.x = fmaf(w, x2.x, acc2.x); acc2.y = fmaf(w, x2.y, acc2.y);
                acc2.z = fmaf(w, x2.z, acc2.z); acc2.w = fmaf(w, x2.w, acc2.w);
                acc3.x = fmaf(w, x3.x, acc3.x); acc3.y = fmaf(w, x3.y, acc3.y);
                acc3.z = fmaf(w, x3.z, acc3.z); acc3.w = fmaf(w, x3.w, acc3.w);
            }
        }

        float4* ob = (float4*)out + (b * V4PB + base);
        __stcs(ob,       acc0);
        __stcs(ob + 256, acc1);
        __stcs(ob + 512, acc2);
        __stcs(ob + 768, acc3);
    }

    // -------- reset the global counters for the next graph replay ---------
    __syncthreads();
    if (t == 0 && atomicAdd(&g_fin, 1u) == GRID - 1) {
        g_fin = 0u;
        g_ready = 0u;
    }
}

// ---------------------------------------------------------------------------
extern "C" void kernel_launch(void* const* d_in, const int* in_sizes, int n_in,
                              void* d_out, int out_size) {
    const float* q    = (const float*)d_in[0];
    const float* k    = (const float*)d_in[1];
    const float* v    = (const float*)d_in[2];
    const float* W    = (const float*)d_in[3];
    const float* bias = (const float*)d_in[4];

    float* out = (float*)d_out;
    const long long out_main = (long long)BATCH * CHW;        // 16777216
    const int write_attn = (out_size >= out_main + BATCH * NAG) ? 1 : 0;
    float* out_attn = out + out_main;

    fused_kernel<<<GRID, 256>>>(q, k, v, W, bias, out, out_attn, write_attn);
}

// round 9
// speedup vs baseline: 1.0088x; 1.0088x over previous
#include <cuda_runtime.h>
#include <cuda_bf16.h>

#define BATCH 32
#define NAG   6
#define KS    256
#define QS    256
#define CHW   (512*32*32)       /* 524288 floats per (b,n) slab */
#define V4PB  (CHW/4)           /* 131072 float4 per (b,n) slab */
#define CHUNKS 8                /* attn kk-chunks per batch (32 rows each) */
#define TILES 2048              /* wsum tiles: 2048 float4 each */
#define GRID  1024              /* exactly 2 tiles per block */

// Scratch (allocation-free rule: __device__ globals). All counters are reset
// inside the kernel so every graph replay starts from identical state.
__device__ float        g_attn[BATCH * NAG];
__device__ float        g_score[BATCH * NAG];
__device__ unsigned int g_cnt[BATCH];
__device__ unsigned int g_ready;     // # batches finalized (0..32)
__device__ unsigned int g_fin;       // # blocks finished (0..GRID)

// ---------------------------------------------------------------------------
// Persistent fused kernel, grid = 1024 x 256.
//  * blocks 0..255 first run one attn chunk: query rows via warp dots ->
//    partial agent scores -> ticketed sparsemax -> g_attn -> g_ready++.
//  * all blocks: wait g_ready==32, stage all 192 weights + per-batch
//    single-agent index, then 2 tiles each of the weighted sum.
//    nz==1 (dominant): pure scale-copy, 8 float4 in flight, no accumulators.
//    nz>=2 (rare):     4-accumulator loop, two halves per tile.
//  * last finishing block resets g_ready/g_fin for the next graph replay.
// ---------------------------------------------------------------------------
__global__ void __launch_bounds__(256)
fused_kernel(const float* __restrict__ q,
             const float* __restrict__ k,
             const float* __restrict__ v,
             const float* __restrict__ W,
             const float* __restrict__ bias,
             float* __restrict__ out,
             float* __restrict__ out_attn,
             int write_attn) {
    const int bid  = blockIdx.x;
    const int t    = threadIdx.x;
    const int wid  = t >> 5, lane = t & 31;

    __shared__ float4 sq4[QS / 4];
    __shared__ float  squery[32];
    __shared__ float  sw[BATCH * NAG];   // all weights, staged once
    __shared__ int    sidx[BATCH];       // nstar if nz==1 else -1

    // ================= attn phase (blocks 0..255 only) ====================
    if (bid < BATCH * CHUNKS) {
        const int ab     = bid >> 3;
        const int kkbase = (bid & 7) << 5;

        if (t < QS / 4) sq4[t] = ((const float4*)(q + ab * QS))[t];
        __syncthreads();

        // warp `wid` computes 4 query rows, 2 at a time
        {
            const int r0 = kkbase + (wid << 2);
            const float4 q0 = sq4[lane], q1 = sq4[lane + 32];
            #pragma unroll
            for (int h = 0; h < 2; h++) {
                const int ra = r0 + 2 * h;
                const float4* wa = (const float4*)(W + ra * QS);
                const float4* wb = (const float4*)(W + (ra + 1) * QS);
                float4 a0 = wa[lane], a1 = wa[lane + 32];
                float4 b0 = wb[lane], b1 = wb[lane + 32];
                float sa = a0.x * q0.x + a0.y * q0.y + a0.z * q0.z + a0.w * q0.w
                         + a1.x * q1.x + a1.y * q1.y + a1.z * q1.z + a1.w * q1.w;
                float sb = b0.x * q0.x + b0.y * q0.y + b0.z * q0.z + b0.w * q0.w
                         + b1.x * q1.x + b1.y * q1.y + b1.z * q1.z + b1.w * q1.w;
                #pragma unroll
                for (int o = 16; o; o >>= 1) {
                    sa += __shfl_xor_sync(0xffffffffu, sa, o);
                    sb += __shfl_xor_sync(0xffffffffu, sb, o);
                }
                if (lane == 0) {
                    squery[(wid << 2) + 2 * h]     = sa + bias[ra];
                    squery[(wid << 2) + 2 * h + 1] = sb + bias[ra + 1];
                }
            }
        }
        __syncthreads();

        // 6 warps -> partial agent scores
        if (wid < NAG) {
            float p = k[(ab * NAG + wid) * KS + kkbase + lane] * squery[lane];
            #pragma unroll
            for (int o = 16; o; o >>= 1) p += __shfl_xor_sync(0xffffffffu, p, o);
            if (lane == 0) atomicAdd(&g_score[ab * NAG + wid], p);
        }

        __threadfence();
        if (t == 0 && atomicAdd(&g_cnt[ab], 1u) == CHUNKS - 1) {
            __threadfence();                      // acquire all partials
            float z[NAG], zs[NAG];
            #pragma unroll
            for (int n = 0; n < NAG; n++) {
                z[n] = g_score[ab * NAG + n];
                zs[n] = z[n];
                g_score[ab * NAG + n] = 0.0f;     // reset for next replay
            }
            g_cnt[ab] = 0u;
            #pragma unroll
            for (int i = 1; i < NAG; i++) {       // insertion sort, descending
                float key = zs[i]; int j = i - 1;
                while (j >= 0 && zs[j] < key) { zs[j + 1] = zs[j]; j--; }
                zs[j + 1] = key;
            }
            float cs[NAG], run = 0.f;
            #pragma unroll
            for (int r = 0; r < NAG; r++) { run += zs[r]; cs[r] = run; }
            int kk = 0;
            #pragma unroll
            for (int r = 1; r <= NAG; r++)
                if (1.0f + (float)r * zs[r - 1] > cs[r - 1]) kk++;
            const float tau = (cs[kk - 1] - 1.0f) / (float)kk;
            #pragma unroll
            for (int n = 0; n < NAG; n++) {
                float p = fmaxf(z[n] - tau, 0.0f);
                g_attn[ab * NAG + n] = p;
                if (write_attn) out_attn[ab * NAG + n] = p;
            }
            __threadfence();                      // publish before counting
            atomicAdd(&g_ready, 1u);
        }
        __syncthreads();
    }

    // ================= wait once, stage weights + fast-path index =========
    if (t == 0) {
        while (*((volatile unsigned int*)&g_ready) != BATCH) __nanosleep(64);
    }
    __syncthreads();
    if (t < BATCH * NAG) sw[t] = __ldcg(&g_attn[t]);
    __syncthreads();
    if (t < BATCH) {
        int nz = 0, ns = 0;
        #pragma unroll
        for (int n = 0; n < NAG; n++)
            if (sw[t * NAG + n] != 0.0f) { nz++; ns = n; }
        sidx[t] = (nz == 1) ? ns : -1;
    }
    __syncthreads();

    // ================= persistent wsum loop (2 tiles/block) ===============
    for (int tau = bid; tau < TILES; tau += GRID) {
        const int b    = tau >> 6;                        // 64 tiles/batch
        const int base = ((tau & 63) << 11) + t;          // float4 idx in slab

        const float4* vb = (const float4*)v + (b * (NAG * V4PB) + base);
        float4*       ob = (float4*)out    + (b * V4PB + base);

        const int ns = sidx[b];
        if (ns >= 0) {
            // ---- fast path: single nonzero agent -> scale-copy, MLP=8 ----
            const float w = sw[b * NAG + ns];
            const float4* p = vb + ns * V4PB;
            float4 x[8];
            #pragma unroll
            for (int i = 0; i < 8; i++) x[i] = __ldcs(p + (i << 8));
            #pragma unroll
            for (int i = 0; i < 8; i++) {
                float4 r;
                r.x = w * x[i].x; r.y = w * x[i].y;
                r.z = w * x[i].z; r.w = w * x[i].w;
                __stcs(ob + (i << 8), r);
            }
        } else {
            // ---- fallback: multi-agent accumulate, two halves of 4 -------
            #pragma unroll
            for (int h = 0; h < 2; h++) {
                const int off = h << 10;                  // 0 or 1024 float4
                float4 acc0 = make_float4(0.f, 0.f, 0.f, 0.f);
                float4 acc1 = acc0, acc2 = acc0, acc3 = acc0;
                #pragma unroll
                for (int n = 0; n < NAG; n++) {
                    const float w = sw[b * NAG + n];
                    if (w != 0.0f) {
                        const float4* p = vb + (n * V4PB + off);
                        float4 x0 = __ldcs(p);
                        float4 x1 = __ldcs(p + 256);
                        float4 x2 = __ldcs(p + 512);
                        float4 x3 = __ldcs(p + 768);
                        acc0.x = fmaf(w, x0.x, acc0.x); acc0.y = fmaf(w, x0.y, acc0.y);
                        acc0.z = fmaf(w, x0.z, acc0.z); acc0.w = fmaf(w, x0.w, acc0.w);
                        acc1.x = fmaf(w, x1.x, acc1.x); acc1.y = fmaf(w, x1.y, acc1.y);
                        acc1.z = fmaf(w, x1.z, acc1.z); acc1.w = fmaf(w, x1.w, acc1.w);
                        acc2.x = fmaf(w, x2.x, acc2.x); acc2.y = fmaf(w, x2.y, acc2.y);
                        acc2.z = fmaf(w, x2.z, acc2.z); acc2.w = fmaf(w, x2.w, acc2.w);
                        acc3.x = fmaf(w, x3.x, acc3.x); acc3.y = fmaf(w, x3.y, acc3.y);
                        acc3.z = fmaf(w, x3.z, acc3.z); acc3.w = fmaf(w, x3.w, acc3.w);
                    }
                }
                __stcs(ob + off,       acc0);
                __stcs(ob + off + 256, acc1);
                __stcs(ob + off + 512, acc2);
                __stcs(ob + off + 768, acc3);
            }
        }
    }

    // -------- reset the global counters for the next graph replay ---------
    __syncthreads();
    if (t == 0 && atomicAdd(&g_fin, 1u) == GRID - 1) {
        g_fin = 0u;
        g_ready = 0u;
    }
}

// ---------------------------------------------------------------------------
extern "C" void kernel_launch(void* const* d_in, const int* in_sizes, int n_in,
                              void* d_out, int out_size) {
    const float* q    = (const float*)d_in[0];
    const float* k    = (const float*)d_in[1];
    const float* v    = (const float*)d_in[2];
    const float* W    = (const float*)d_in[3];
    const float* bias = (const float*)d_in[4];

    float* out = (float*)d_out;
    const long long out_main = (long long)BATCH * CHW;        // 16777216
    const int write_attn = (out_size >= out_main + BATCH * NAG) ? 1 : 0;
    float* out_attn = out + out_main;

    fused_kernel<<<GRID, 256>>>(q, k, v, W, bias, out, out_attn, write_attn);
}